// round 13
// baseline (speedup 1.0000x reference)
#include <cuda_runtime.h>
#include <cuda_bf16.h>
#include <mma.h>
#include <cstdint>

using namespace nvcuda;

#define T_STEPS 64
#define N_ROWS  2048
#define DR2     512
#define KDIM    1024
#define DECAY_F 0.6065306597126334f

typedef wmma::fragment<wmma::matrix_a, 16,16,16, __nv_bfloat16, wmma::row_major> FragA;
typedef wmma::fragment<wmma::matrix_b, 16,16,16, __nv_bfloat16, wmma::col_major> FragB;
typedef wmma::fragment<wmma::accumulator, 16,16,16, float> FragC;

// scratch: 2-component bf16 splits
__device__ __nv_bfloat16 g_A0[(size_t)T_STEPS * N_ROWS * DR2];
__device__ __nv_bfloat16 g_A1[(size_t)T_STEPS * N_ROWS * DR2];
__device__ __nv_bfloat16 g_W0[(size_t)DR2 * DR2];   // [n][k], bottom half of w1, transposed
__device__ __nv_bfloat16 g_W1[(size_t)DR2 * DR2];

__device__ __forceinline__ unsigned smem_u32(const void* p) {
    return (unsigned)__cvta_generic_to_shared(p);
}
__device__ __forceinline__ unsigned long long dup2(float x) {
    unsigned long long r; asm("mov.b64 %0, {%1, %1};" : "=l"(r) : "f"(x)); return r;
}
#define CPASYNC(dst, src) asm volatile("cp.async.cg.shared.global [%0], [%1], 16;" :: "r"(dst), "l"(src))
#define CPCOMMIT()        asm volatile("cp.async.commit_group;")
#define CPWAIT(n)         asm volatile("cp.async.wait_group %0;" :: "n"(n) : "memory")

__device__ __forceinline__ void split2(float v, __nv_bfloat16& c0, __nv_bfloat16& c1) {
    c0 = __float2bfloat16_rn(v);
    c1 = __float2bfloat16_rn(v - __bfloat162float(c0));
}

// ======================= prep: split static into 2 bf16 components =======================
__global__ void prep_a2(const float4* __restrict__ src)
{
    size_t i = (size_t)blockIdx.x * blockDim.x + threadIdx.x;
    float4 v = src[i];
    __nv_bfloat16 a0[4], a1[4];
    split2(v.x, a0[0], a1[0]);
    split2(v.y, a0[1], a1[1]);
    split2(v.z, a0[2], a1[2]);
    split2(v.w, a0[3], a1[3]);
    ((__nv_bfloat162*)g_A0)[i*2]   = __halves2bfloat162(a0[0], a0[1]);
    ((__nv_bfloat162*)g_A0)[i*2+1] = __halves2bfloat162(a0[2], a0[3]);
    ((__nv_bfloat162*)g_A1)[i*2]   = __halves2bfloat162(a1[0], a1[1]);
    ((__nv_bfloat162*)g_A1)[i*2+1] = __halves2bfloat162(a1[2], a1[3]);
}

// ======================= prep: transpose + 2-split bottom half of w1 =======================
__global__ void prep_w2(const float* __restrict__ w1)
{
    __shared__ float tile[32][33];
    const int kb = blockIdx.x * 32, nb = blockIdx.y * 32;
    const int tx = threadIdx.x & 31, ty = threadIdx.x >> 5;
    #pragma unroll
    for (int r = 0; r < 32; r += 8)
        tile[ty + r][tx] = w1[(size_t)(DR2 + kb + ty + r) * DR2 + nb + tx];
    __syncthreads();
    #pragma unroll
    for (int r = 0; r < 32; r += 8) {
        int n = nb + ty + r, k = kb + tx;
        __nv_bfloat16 c0, c1;
        split2(tile[tx][ty + r], c0, c1);
        g_W0[(size_t)n * DR2 + k] = c0;
        g_W1[(size_t)n * DR2 + k] = c1;
    }
}

// ======================= pass 1: G = static @ W_bot (wmma bf16, 4 products) =======================
// CTA tile 128x128, K=512 in 16 chunks of 32, double-buffered. 2 CTAs/SM.
// grid.x = n-tiles (4) so consecutive CTAs share the A tile via L2.
#define KP      40
#define ACOMP1  (128 * KP * 2)      // 10240 B per component
#define STG1    (4 * ACOMP1)        // A0|A1|B0|B1 = 40960 B
#define P1_SMEM (2 * STG1)          // 81920

__global__ void __launch_bounds__(256, 2)
pass1_kernel(float* __restrict__ C)
{
    extern __shared__ char sm[];
    const int tid = threadIdx.x;
    const int wid = tid >> 5;
    const size_t m0 = (size_t)blockIdx.y * 128;
    const size_t n0 = (size_t)blockIdx.x * 128;

    auto loadAB = [&](int c, int s) {
        char* S = sm + s * STG1;
        #pragma unroll
        for (int r = 0; r < 4; ++r) {       // A: 2 comp x 128 rows x 4 vec16
            int id = tid + r * 256;
            int comp = id >> 9, rem = id & 511;
            int row = rem >> 2, kq = rem & 3;
            const __nv_bfloat16* base = comp ? g_A1 : g_A0;
            const __nv_bfloat16* src = base + (m0 + row) * DR2 + c * 32 + kq * 8;
            CPASYNC(smem_u32(S + comp * ACOMP1 + row * (KP*2) + kq * 16), src);
        }
        #pragma unroll
        for (int r = 0; r < 4; ++r) {       // B: 2 comp x 128 rows x 4 vec16
            int id = tid + r * 256;
            int comp = id >> 9, rem = id & 511;
            int row = rem >> 2, kq = rem & 3;
            const __nv_bfloat16* base = comp ? g_W1 : g_W0;
            const __nv_bfloat16* src = base + (n0 + row) * DR2 + c * 32 + kq * 8;
            CPASYNC(smem_u32(S + 2 * ACOMP1 + comp * ACOMP1 + row * (KP*2) + kq * 16), src);
        }
        CPCOMMIT();
    };

    FragC acc[2][4];
    #pragma unroll
    for (int i = 0; i < 2; ++i)
        #pragma unroll
        for (int j = 0; j < 4; ++j) wmma::fill_fragment(acc[i][j], 0.0f);

    const int mw = (wid >> 1) * 32;     // 4 m-slots of 32
    const int nw = (wid & 1) * 64;      // 2 n-slots of 64

    loadAB(0, 0);
    for (int c = 0; c < 16; ++c) {
        if (c < 15) { loadAB(c + 1, (c + 1) & 1); CPWAIT(1); } else CPWAIT(0);
        __syncthreads();
        char* S = sm + (c & 1) * STG1;
        const __nv_bfloat16* A0 = (const __nv_bfloat16*)(S);
        const __nv_bfloat16* A1 = (const __nv_bfloat16*)(S + ACOMP1);
        const __nv_bfloat16* B0 = (const __nv_bfloat16*)(S + 2 * ACOMP1);
        const __nv_bfloat16* B1 = (const __nv_bfloat16*)(S + 3 * ACOMP1);
        #pragma unroll
        for (int ks = 0; ks < 2; ++ks) {
            FragA a0[2], a1[2];
            #pragma unroll
            for (int i = 0; i < 2; ++i) {
                int ro = (mw + i * 16) * KP + ks * 16;
                wmma::load_matrix_sync(a0[i], A0 + ro, KP);
                wmma::load_matrix_sync(a1[i], A1 + ro, KP);
            }
            #pragma unroll
            for (int j = 0; j < 4; ++j) {
                int ro = (nw + j * 16) * KP + ks * 16;
                FragB b0, b1;
                wmma::load_matrix_sync(b0, B0 + ro, KP);
                wmma::load_matrix_sync(b1, B1 + ro, KP);
                #pragma unroll
                for (int i = 0; i < 2; ++i) {
                    wmma::mma_sync(acc[i][j], a0[i], b0, acc[i][j]);
                    wmma::mma_sync(acc[i][j], a0[i], b1, acc[i][j]);
                    wmma::mma_sync(acc[i][j], a1[i], b0, acc[i][j]);
                    wmma::mma_sync(acc[i][j], a1[i], b1, acc[i][j]);
                }
            }
        }
        __syncthreads();
    }
    #pragma unroll
    for (int i = 0; i < 2; ++i)
        #pragma unroll
        for (int j = 0; j < 4; ++j)
            wmma::store_matrix_sync(C + (m0 + mw + i * 16) * DR2 + n0 + nw + j * 16,
                                    acc[i][j], DR2, wmma::mem_row_major);
}

// ======================= pass 2: fp32 recurrence, split-K x4, 5-stage deep pipeline =======================
#define NTH2    512
#define XPITCH  516
#define NSTG    5
#define CHUNKF  8192            // floats per stage (32KB): 4 q x 4 r x 512
#define KCQ     4               // k-rows per quarter per chunk
#define NCHK    32              // chunks per step
// smem float offsets
#define W_OFF   0               // NSTG * 8192 = 40960 floats (160KB)
#define H_OFF   (NSTG * CHUNKF)         // 16 x 516
#define THR_OFF (H_OFF + 16 * XPITCH)   // 16
#define SM2_BYTES ((THR_OFF + 16) * 4)

__global__ void __launch_bounds__(NTH2, 1)
evo_kernel(const float* __restrict__ g_thr,
           const float* __restrict__ g_h0,
           const float* __restrict__ g_w1,
           float* __restrict__ g_out)
{
    extern __shared__ char sm[];
    float* smf   = (float*)sm;
    float* w_sh  = smf + W_OFF;
    float* h_sh  = smf + H_OFF;
    float* thr_s = smf + THR_OFF;

    float* out_dyn  = g_out;
    float* out_fin  = g_out + (size_t)T_STEPS * N_ROWS * DR2;
    float* out_diff = out_fin + (size_t)N_ROWS * DR2;

    const int tid = threadIdx.x;
    const int r0  = blockIdx.x * 16;
    const int kq  = tid >> 7;          // k-quarter 0..3
    const int mt  = (tid >> 6) & 1;    // row-group (8 rows)
    const int jt  = tid & 63;          // 8 cols (4 float2)

    auto loadW = [&](int c) {          // one 32KB chunk -> stage c%NSTG (4 cp.async/thread)
        unsigned dstb = smem_u32(w_sh + (c % NSTG) * CHUNKF);
        #pragma unroll
        for (int i = 0; i < 4; ++i) {
            int idx = tid + i * NTH2;
            int q = idx >> 9, rem = idx & 511;
            int r = rem >> 7, f4 = rem & 127;
            const char* src = (const char*)(g_w1 + ((size_t)(q * 128 + c * KCQ + r)) * DR2 + f4 * 4);
            CPASYNC(dstb + (unsigned)((q * 4 + r) * 512 + f4 * 4) * 4u, src);
        }
        CPCOMMIT();
    };

    // ---- init: h0 -> h_sh ----
    {
        const float4* src = (const float4*)(g_h0 + (size_t)r0 * DR2);
        #pragma unroll
        for (int i = 0; i < 4; ++i) {
            int idx = tid + i * NTH2;
            int row = idx >> 7, f4 = idx & 127;
            *(float4*)(h_sh + row * XPITCH + f4 * 4) = src[idx];
        }
    }
    loadW(0); loadW(1); loadW(2); loadW(3);
    __syncthreads();

    unsigned long long acc[8][4];

    for (int t = 0; t < T_STEPS; ++t) {
        if (tid < 16) thr_s[tid] = g_thr[(size_t)t * N_ROWS + r0 + tid];

        #pragma unroll
        for (int a = 0; a < 8; ++a)
            #pragma unroll
            for (int b = 0; b < 4; ++b) acc[a][b] = 0ull;

        const float* xbase = h_sh + mt * 8 * XPITCH + kq * 128;

        for (int c = 0; c < NCHK; ++c) {
            // wait for chunk c (issued 4 chunks ago); pending groups tracked per-thread
            if      (c <= NCHK - 4) CPWAIT(3);
            else if (c == NCHK - 3) CPWAIT(2);
            else if (c == NCHK - 2) CPWAIT(1);
            else                    CPWAIT(0);
            __syncthreads();                 // chunk c visible to all; stage (c-1)%5 free
            if (c + 4 < NCHK) loadW(c + 4);  // refill stage (c+4)%5 == (c-1)%5

            const float* wb = w_sh + (c % NSTG) * CHUNKF + kq * 2048;
            const float* xb = xbase + c * KCQ;

            #pragma unroll
            for (int kk = 0; kk < KCQ; ++kk) {
                unsigned long long xv[8];
                #pragma unroll
                for (int mi = 0; mi < 8; ++mi)
                    xv[mi] = dup2(xb[mi * XPITCH + kk]);
                const unsigned long long* wrow = (const unsigned long long*)(wb + kk * 512);
                unsigned long long wv[4];
                #pragma unroll
                for (int jj = 0; jj < 4; ++jj) wv[jj] = wrow[jt + 64 * jj];
                #pragma unroll
                for (int mi = 0; mi < 8; ++mi)
                    #pragma unroll
                    for (int jj = 0; jj < 4; ++jj)
                        asm("fma.rn.f32x2 %0, %1, %2, %0;"
                            : "+l"(acc[mi][jj]) : "l"(xv[mi]), "l"(wv[jj]));
            }
        }
        __syncthreads();   // all compute done before P overwrites stages 0-3

        // ---- write partials to P (aliases stages 0-3: P[q] at q*8192 floats) ----
        {
            unsigned long long* P = (unsigned long long*)(w_sh + kq * 8192);
            #pragma unroll
            for (int mi = 0; mi < 8; ++mi)
                #pragma unroll
                for (int jj = 0; jj < 4; ++jj)
                    P[((mt * 8 + mi) * 512 + jt * 2 + 128 * jj) >> 1] = acc[mi][jj];
        }
        __syncthreads();

        // ---- gate: reduce 4 partials + G (direct LDG), sigmoid, update h, write outputs ----
        {
            int r = tid >> 5, cs = tid & 31;
            float th = thr_s[r], om = 1.0f - th;
            size_t rowoff = (size_t)(r0 + r) * DR2;
            float* dynp  = out_dyn  + (size_t)t * N_ROWS * DR2 + rowoff;
            float* finp  = out_fin  + rowoff;
            float* diffp = out_diff + (size_t)(t - 1) * N_ROWS * DR2 + rowoff;
            #pragma unroll
            for (int w = 0; w < 4; ++w) {
                int col = cs * 16 + w * 4;
                float4 gg = *(const float4*)(dynp + col);    // G staged by pass 1
                float4 p0 = *(float4*)(w_sh + 0 * 8192 + r * 512 + col);
                float4 p1 = *(float4*)(w_sh + 1 * 8192 + r * 512 + col);
                float4 p2 = *(float4*)(w_sh + 2 * 8192 + r * 512 + col);
                float4 p3 = *(float4*)(w_sh + 3 * 8192 + r * 512 + col);
                float4 ho = *(float4*)(h_sh + r * XPITCH + col);
                float mm[4] = { p0.x + p1.x + p2.x + p3.x + gg.x,
                                p0.y + p1.y + p2.y + p3.y + gg.y,
                                p0.z + p1.z + p2.z + p3.z + gg.z,
                                p0.w + p1.w + p2.w + p3.w + gg.w };
                float hv[4] = { ho.x, ho.y, ho.z, ho.w };
                float nv[4];
                #pragma unroll
                for (int e = 0; e < 4; ++e)
                    nv[e] = DECAY_F / (1.0f + __expf(-(mm[e] * th + hv[e] * om)));
                *(float4*)(h_sh + r * XPITCH + col) = make_float4(nv[0], nv[1], nv[2], nv[3]);
                if (t > 0) {
                    *(float4*)(dynp + col)  = make_float4(nv[0], nv[1], nv[2], nv[3]);
                    *(float4*)(diffp + col) = make_float4(nv[0] - hv[0], nv[1] - hv[1],
                                                          nv[2] - hv[2], nv[3] - hv[3]);
                } else {
                    *(float4*)(dynp + col) = make_float4(hv[0], hv[1], hv[2], hv[3]);  // dyn[0]=h0
                }
                if (t == T_STEPS - 1)
                    *(float4*)(finp + col) = make_float4(nv[0], nv[1], nv[2], nv[3]);
            }
        }
        __syncthreads();

        // ---- prologue for next step: chunks 0-3 into stages 0-3 ----
        if (t + 1 < T_STEPS) {
            loadW(0); loadW(1); loadW(2); loadW(3);
        }
    }
}

extern "C" void kernel_launch(void* const* d_in, const int* in_sizes, int n_in,
                              void* d_out, int out_size)
{
    (void)in_sizes; (void)n_in; (void)out_size;
    const float* g_static = (const float*)d_in[0];
    const float* g_thr    = (const float*)d_in[1];
    const float* g_h0     = (const float*)d_in[2];
    const float* g_w1     = (const float*)d_in[3];
    float* out = (float*)d_out;

    // prep: 2-component bf16 splits
    prep_w2<<<dim3(DR2 / 32, DR2 / 32), 256>>>(g_w1);
    prep_a2<<<(T_STEPS * N_ROWS * DR2 / 4) / 256, 256>>>((const float4*)g_static);

    // pass 1: G = static @ W_bot (4 products) -> staged into dyn region
    cudaFuncSetAttribute(pass1_kernel, cudaFuncAttributeMaxDynamicSharedMemorySize, P1_SMEM);
    dim3 grid1(DR2 / 128, T_STEPS * N_ROWS / 128);   // x = n-tiles (A shared in L2)
    pass1_kernel<<<grid1, 256, P1_SMEM>>>(out);

    // pass 2: fp32 recurrence, split-K x4, deep pipeline
    cudaFuncSetAttribute(evo_kernel, cudaFuncAttributeMaxDynamicSharedMemorySize, SM2_BYTES);
    evo_kernel<<<N_ROWS / 16, NTH2, SM2_BYTES>>>(g_thr, g_h0, g_w1, out);
}

// round 14
// speedup vs baseline: 1.0534x; 1.0534x over previous
#include <cuda_runtime.h>
#include <cuda_bf16.h>
#include <mma.h>
#include <cstdint>

using namespace nvcuda;

#define T_STEPS 64
#define N_ROWS  2048
#define DR2     512
#define KDIM    1024
#define DECAY_F 0.6065306597126334f

typedef wmma::fragment<wmma::matrix_a, 16,16,16, __nv_bfloat16, wmma::row_major> FragA;
typedef wmma::fragment<wmma::matrix_b, 16,16,16, __nv_bfloat16, wmma::col_major> FragB;
typedef wmma::fragment<wmma::accumulator, 16,16,16, float> FragC;

// scratch: 2-component bf16 splits
__device__ __nv_bfloat16 g_A0[(size_t)T_STEPS * N_ROWS * DR2];
__device__ __nv_bfloat16 g_A1[(size_t)T_STEPS * N_ROWS * DR2];
__device__ __nv_bfloat16 g_W0[(size_t)DR2 * DR2];   // [n][k], bottom half of w1, transposed
__device__ __nv_bfloat16 g_W1[(size_t)DR2 * DR2];

__device__ __forceinline__ unsigned smem_u32(const void* p) {
    return (unsigned)__cvta_generic_to_shared(p);
}
__device__ __forceinline__ unsigned long long dup2(float x) {
    unsigned long long r; asm("mov.b64 %0, {%1, %1};" : "=l"(r) : "f"(x)); return r;
}
#define CPASYNC(dst, src) asm volatile("cp.async.cg.shared.global [%0], [%1], 16;" :: "r"(dst), "l"(src))
#define CPCOMMIT()        asm volatile("cp.async.commit_group;")
#define CPWAIT(n)         asm volatile("cp.async.wait_group %0;" :: "n"(n) : "memory")

__device__ __forceinline__ void split2(float v, __nv_bfloat16& c0, __nv_bfloat16& c1) {
    c0 = __float2bfloat16_rn(v);
    c1 = __float2bfloat16_rn(v - __bfloat162float(c0));
}

// ======================= prep: split static into 2 bf16 components =======================
__global__ void prep_a2(const float4* __restrict__ src)
{
    size_t i = (size_t)blockIdx.x * blockDim.x + threadIdx.x;
    float4 v = src[i];
    __nv_bfloat16 a0[4], a1[4];
    split2(v.x, a0[0], a1[0]);
    split2(v.y, a0[1], a1[1]);
    split2(v.z, a0[2], a1[2]);
    split2(v.w, a0[3], a1[3]);
    ((__nv_bfloat162*)g_A0)[i*2]   = __halves2bfloat162(a0[0], a0[1]);
    ((__nv_bfloat162*)g_A0)[i*2+1] = __halves2bfloat162(a0[2], a0[3]);
    ((__nv_bfloat162*)g_A1)[i*2]   = __halves2bfloat162(a1[0], a1[1]);
    ((__nv_bfloat162*)g_A1)[i*2+1] = __halves2bfloat162(a1[2], a1[3]);
}

// ======================= prep: transpose + 2-split bottom half of w1 =======================
__global__ void prep_w2(const float* __restrict__ w1)
{
    __shared__ float tile[32][33];
    const int kb = blockIdx.x * 32, nb = blockIdx.y * 32;
    const int tx = threadIdx.x & 31, ty = threadIdx.x >> 5;
    #pragma unroll
    for (int r = 0; r < 32; r += 8)
        tile[ty + r][tx] = w1[(size_t)(DR2 + kb + ty + r) * DR2 + nb + tx];
    __syncthreads();
    #pragma unroll
    for (int r = 0; r < 32; r += 8) {
        int n = nb + ty + r, k = kb + tx;
        __nv_bfloat16 c0, c1;
        split2(tile[tx][ty + r], c0, c1);
        g_W0[(size_t)n * DR2 + k] = c0;
        g_W1[(size_t)n * DR2 + k] = c1;
    }
}

// ======================= pass 1: G = static @ W_bot (wmma bf16, 4 products) =======================
// CTA tile 128x128, K=512 in 16 chunks of 32, double-buffered. 2 CTAs/SM.
// grid.x = n-tiles (4) so consecutive CTAs share the A tile via L2.
#define KP      40
#define ACOMP1  (128 * KP * 2)      // 10240 B per component
#define STG1    (4 * ACOMP1)        // A0|A1|B0|B1 = 40960 B
#define P1_SMEM (2 * STG1)          // 81920

__global__ void __launch_bounds__(256, 2)
pass1_kernel(float* __restrict__ C)
{
    extern __shared__ char sm[];
    const int tid = threadIdx.x;
    const int wid = tid >> 5;
    const size_t m0 = (size_t)blockIdx.y * 128;
    const size_t n0 = (size_t)blockIdx.x * 128;

    auto loadAB = [&](int c, int s) {
        char* S = sm + s * STG1;
        #pragma unroll
        for (int r = 0; r < 4; ++r) {       // A: 2 comp x 128 rows x 4 vec16
            int id = tid + r * 256;
            int comp = id >> 9, rem = id & 511;
            int row = rem >> 2, kq = rem & 3;
            const __nv_bfloat16* base = comp ? g_A1 : g_A0;
            const __nv_bfloat16* src = base + (m0 + row) * DR2 + c * 32 + kq * 8;
            CPASYNC(smem_u32(S + comp * ACOMP1 + row * (KP*2) + kq * 16), src);
        }
        #pragma unroll
        for (int r = 0; r < 4; ++r) {       // B: 2 comp x 128 rows x 4 vec16
            int id = tid + r * 256;
            int comp = id >> 9, rem = id & 511;
            int row = rem >> 2, kq = rem & 3;
            const __nv_bfloat16* base = comp ? g_W1 : g_W0;
            const __nv_bfloat16* src = base + (n0 + row) * DR2 + c * 32 + kq * 8;
            CPASYNC(smem_u32(S + 2 * ACOMP1 + comp * ACOMP1 + row * (KP*2) + kq * 16), src);
        }
        CPCOMMIT();
    };

    FragC acc[2][4];
    #pragma unroll
    for (int i = 0; i < 2; ++i)
        #pragma unroll
        for (int j = 0; j < 4; ++j) wmma::fill_fragment(acc[i][j], 0.0f);

    const int mw = (wid >> 1) * 32;     // 4 m-slots of 32
    const int nw = (wid & 1) * 64;      // 2 n-slots of 64

    loadAB(0, 0);
    for (int c = 0; c < 16; ++c) {
        if (c < 15) { loadAB(c + 1, (c + 1) & 1); CPWAIT(1); } else CPWAIT(0);
        __syncthreads();
        char* S = sm + (c & 1) * STG1;
        const __nv_bfloat16* A0 = (const __nv_bfloat16*)(S);
        const __nv_bfloat16* A1 = (const __nv_bfloat16*)(S + ACOMP1);
        const __nv_bfloat16* B0 = (const __nv_bfloat16*)(S + 2 * ACOMP1);
        const __nv_bfloat16* B1 = (const __nv_bfloat16*)(S + 3 * ACOMP1);
        #pragma unroll
        for (int ks = 0; ks < 2; ++ks) {
            FragA a0[2], a1[2];
            #pragma unroll
            for (int i = 0; i < 2; ++i) {
                int ro = (mw + i * 16) * KP + ks * 16;
                wmma::load_matrix_sync(a0[i], A0 + ro, KP);
                wmma::load_matrix_sync(a1[i], A1 + ro, KP);
            }
            #pragma unroll
            for (int j = 0; j < 4; ++j) {
                int ro = (nw + j * 16) * KP + ks * 16;
                FragB b0, b1;
                wmma::load_matrix_sync(b0, B0 + ro, KP);
                wmma::load_matrix_sync(b1, B1 + ro, KP);
                #pragma unroll
                for (int i = 0; i < 2; ++i) {
                    wmma::mma_sync(acc[i][j], a0[i], b0, acc[i][j]);
                    wmma::mma_sync(acc[i][j], a0[i], b1, acc[i][j]);
                    wmma::mma_sync(acc[i][j], a1[i], b0, acc[i][j]);
                    wmma::mma_sync(acc[i][j], a1[i], b1, acc[i][j]);
                }
            }
        }
        __syncthreads();
    }
    #pragma unroll
    for (int i = 0; i < 2; ++i)
        #pragma unroll
        for (int j = 0; j < 4; ++j)
            wmma::store_matrix_sync(C + (m0 + mw + i * 16) * DR2 + n0 + nw + j * 16,
                                    acc[i][j], DR2, wmma::mem_row_major);
}

// ======================= pass 2: fp32 recurrence, split-K x4, x-in-registers =======================
#define NTH2    512
#define XPITCH  516
#define KCQ     8               // k-rows per quarter per chunk
#define NCHK    16              // chunks per step (16*8 = 128 rows/quarter)
// smem float offsets
#define W_OFF   0               // 2 stages x 16384 floats
#define H_OFF   32768           // 16 x 516
#define G_OFF   41024           // 16 x 516
#define THR_OFF 49280           // 16
#define SM2_BYTES (49296 * 4)

__global__ void __launch_bounds__(NTH2, 1)
evo_kernel(const float* __restrict__ g_thr,
           const float* __restrict__ g_h0,
           const float* __restrict__ g_w1,
           float* __restrict__ g_out)
{
    extern __shared__ char sm[];
    float* smf   = (float*)sm;
    float* w_sh  = smf + W_OFF;
    float* h_sh  = smf + H_OFF;
    float* g_sh  = smf + G_OFF;
    float* thr_s = smf + THR_OFF;

    float* out_dyn  = g_out;
    float* out_fin  = g_out + (size_t)T_STEPS * N_ROWS * DR2;
    float* out_diff = out_fin + (size_t)N_ROWS * DR2;

    const int tid = threadIdx.x;
    const int r0  = blockIdx.x * 16;
    const int kq  = tid >> 7;          // k-quarter 0..3
    const int mt  = (tid >> 6) & 1;    // row-group (8 rows)
    const int jt  = tid & 63;          // 8 cols (4 float2)

    auto loadW = [&](int c, int s) {   // one chunk: 4 quarters x 8 rows x 512 = 64KB
        unsigned dstb = smem_u32(w_sh + s * 16384);
        #pragma unroll
        for (int i = 0; i < 8; ++i) {
            int idx = tid + i * NTH2;
            int q = idx >> 10, rem = idx & 1023;
            int r = rem >> 7, f4 = rem & 127;
            const char* src = (const char*)(g_w1 + ((size_t)(q * 128 + c * KCQ + r)) * DR2 + f4 * 4);
            CPASYNC(dstb + (unsigned)((q * 8 + r) * 512 + f4 * 4) * 4u, src);
        }
    };
    auto loadG = [&](int t) {          // G[t] tile -> g_sh (pitch 516)
        #pragma unroll
        for (int i = 0; i < 4; ++i) {
            int idx = tid + i * NTH2;
            int row = idx >> 7, f4 = idx & 127;
            const char* src = (const char*)(out_dyn + ((size_t)t * N_ROWS + r0 + row) * DR2 + f4 * 4);
            CPASYNC(smem_u32(g_sh + row * XPITCH + f4 * 4), src);
        }
    };

    // ---- init: h0 -> h_sh ----
    {
        const float4* src = (const float4*)(g_h0 + (size_t)r0 * DR2);
        #pragma unroll
        for (int i = 0; i < 4; ++i) {
            int idx = tid + i * NTH2;
            int row = idx >> 7, f4 = idx & 127;
            *(float4*)(h_sh + row * XPITCH + f4 * 4) = src[idx];
        }
    }
    loadW(0, 0);
    loadG(0);
    CPCOMMIT();
    __syncthreads();

    unsigned long long acc[8][4];

    for (int t = 0; t < T_STEPS; ++t) {
        if (tid < 16) thr_s[tid] = g_thr[(size_t)t * N_ROWS + r0 + tid];

        #pragma unroll
        for (int a = 0; a < 8; ++a)
            #pragma unroll
            for (int b = 0; b < 4; ++b) acc[a][b] = 0ull;

        const float* xbase = h_sh + mt * 8 * XPITCH + kq * 128;

        for (int c = 0; c < NCHK; ++c) {
            if (c < NCHK - 1) { loadW(c + 1, (c + 1) & 1); CPCOMMIT(); CPWAIT(1); }
            else CPWAIT(0);
            __syncthreads();

            const float* wb = w_sh + (c & 1) * 16384 + kq * 4096;
            const float* xb = xbase + c * KCQ;

            #pragma unroll
            for (int half = 0; half < 2; ++half) {
                // x for this half-chunk into registers (broadcast LDS.128, conflict-free)
                float4 xr[8];
                #pragma unroll
                for (int mi = 0; mi < 8; ++mi)
                    xr[mi] = *(const float4*)(xb + mi * XPITCH + half * 4);
                #pragma unroll
                for (int kk = 0; kk < 4; ++kk) {
                    const unsigned long long* wrow =
                        (const unsigned long long*)(wb + (half * 4 + kk) * 512);
                    unsigned long long wv[4];
                    #pragma unroll
                    for (int jj = 0; jj < 4; ++jj) wv[jj] = wrow[jt + 64 * jj];
                    #pragma unroll
                    for (int mi = 0; mi < 8; ++mi) {
                        float xs = (kk == 0) ? xr[mi].x : (kk == 1) ? xr[mi].y
                                 : (kk == 2) ? xr[mi].z : xr[mi].w;
                        unsigned long long xv = dup2(xs);
                        #pragma unroll
                        for (int jj = 0; jj < 4; ++jj)
                            asm("fma.rn.f32x2 %0, %1, %2, %0;"
                                : "+l"(acc[mi][jj]) : "l"(xv), "l"(wv[jj]));
                    }
                }
            }
            __syncthreads();
        }

        // ---- write partials to P (aliases both W stages: P[q] at q*8192 floats) ----
        {
            unsigned long long* P = (unsigned long long*)(w_sh + kq * 8192);
            #pragma unroll
            for (int mi = 0; mi < 8; ++mi)
                #pragma unroll
                for (int jj = 0; jj < 4; ++jj)
                    P[((mt * 8 + mi) * 512 + jt * 2 + 128 * jj) >> 1] = acc[mi][jj];
        }
        __syncthreads();

        // ---- gate: reduce 4 partials + G, sigmoid, update h, write outputs ----
        {
            int r = tid >> 5, cs = tid & 31;
            float th = thr_s[r], om = 1.0f - th;
            size_t rowoff = (size_t)(r0 + r) * DR2;
            float* dynp  = out_dyn  + (size_t)t * N_ROWS * DR2 + rowoff;
            float* finp  = out_fin  + rowoff;
            float* diffp = out_diff + (size_t)(t - 1) * N_ROWS * DR2 + rowoff;
            #pragma unroll
            for (int w = 0; w < 4; ++w) {
                int col = cs * 16 + w * 4;
                float4 p0 = *(float4*)(w_sh + 0 * 8192 + r * 512 + col);
                float4 p1 = *(float4*)(w_sh + 1 * 8192 + r * 512 + col);
                float4 p2 = *(float4*)(w_sh + 2 * 8192 + r * 512 + col);
                float4 p3 = *(float4*)(w_sh + 3 * 8192 + r * 512 + col);
                float4 gg = *(float4*)(g_sh + r * XPITCH + col);
                float4 ho = *(float4*)(h_sh + r * XPITCH + col);
                float mm[4] = { p0.x + p1.x + p2.x + p3.x + gg.x,
                                p0.y + p1.y + p2.y + p3.y + gg.y,
                                p0.z + p1.z + p2.z + p3.z + gg.z,
                                p0.w + p1.w + p2.w + p3.w + gg.w };
                float hv[4] = { ho.x, ho.y, ho.z, ho.w };
                float nv[4];
                #pragma unroll
                for (int e = 0; e < 4; ++e)
                    nv[e] = DECAY_F / (1.0f + __expf(-(mm[e] * th + hv[e] * om)));
                *(float4*)(h_sh + r * XPITCH + col) = make_float4(nv[0], nv[1], nv[2], nv[3]);
                if (t > 0) {
                    *(float4*)(dynp + col)  = make_float4(nv[0], nv[1], nv[2], nv[3]);
                    *(float4*)(diffp + col) = make_float4(nv[0] - hv[0], nv[1] - hv[1],
                                                          nv[2] - hv[2], nv[3] - hv[3]);
                } else {
                    *(float4*)(dynp + col) = make_float4(hv[0], hv[1], hv[2], hv[3]);  // dyn[0]=h0
                }
                if (t == T_STEPS - 1)
                    *(float4*)(finp + col) = make_float4(nv[0], nv[1], nv[2], nv[3]);
            }
        }
        __syncthreads();

        // ---- tail prefetch: next step's W chunk 0 + G[t+1] ----
        if (t + 1 < T_STEPS) {
            loadW(0, 0);
            loadG(t + 1);
            CPCOMMIT();
        }
    }
}

extern "C" void kernel_launch(void* const* d_in, const int* in_sizes, int n_in,
                              void* d_out, int out_size)
{
    (void)in_sizes; (void)n_in; (void)out_size;
    const float* g_static = (const float*)d_in[0];
    const float* g_thr    = (const float*)d_in[1];
    const float* g_h0     = (const float*)d_in[2];
    const float* g_w1     = (const float*)d_in[3];
    float* out = (float*)d_out;

    // prep: 2-component bf16 splits
    prep_w2<<<dim3(DR2 / 32, DR2 / 32), 256>>>(g_w1);
    prep_a2<<<(T_STEPS * N_ROWS * DR2 / 4) / 256, 256>>>((const float4*)g_static);

    // pass 1: G = static @ W_bot (4 products) -> staged into dyn region
    cudaFuncSetAttribute(pass1_kernel, cudaFuncAttributeMaxDynamicSharedMemorySize, P1_SMEM);
    dim3 grid1(DR2 / 128, T_STEPS * N_ROWS / 128);   // x = n-tiles (A shared in L2)
    pass1_kernel<<<grid1, 256, P1_SMEM>>>(out);

    // pass 2: fp32 recurrence, split-K x4, x-in-registers
    cudaFuncSetAttribute(evo_kernel, cudaFuncAttributeMaxDynamicSharedMemorySize, SM2_BYTES);
    evo_kernel<<<N_ROWS / 16, NTH2, SM2_BYTES>>>(g_thr, g_h0, g_w1, out);
}

// round 15
// speedup vs baseline: 1.0874x; 1.0323x over previous
#include <cuda_runtime.h>
#include <cuda_bf16.h>
#include <mma.h>
#include <cstdint>

using namespace nvcuda;

#define T_STEPS 64
#define N_ROWS  2048
#define DR2     512
#define KDIM    1024
#define DECAY_F 0.6065306597126334f

typedef wmma::fragment<wmma::matrix_a, 16,16,16, __nv_bfloat16, wmma::row_major> FragA;
typedef wmma::fragment<wmma::matrix_b, 16,16,16, __nv_bfloat16, wmma::col_major> FragB;
typedef wmma::fragment<wmma::accumulator, 16,16,16, float> FragC;

// scratch: 2-component bf16 splits
__device__ __nv_bfloat16 g_A0[(size_t)T_STEPS * N_ROWS * DR2];
__device__ __nv_bfloat16 g_A1[(size_t)T_STEPS * N_ROWS * DR2];
__device__ __nv_bfloat16 g_W0[(size_t)DR2 * DR2];   // [n][k], bottom half of w1, transposed
__device__ __nv_bfloat16 g_W1[(size_t)DR2 * DR2];

__device__ __forceinline__ unsigned smem_u32(const void* p) {
    return (unsigned)__cvta_generic_to_shared(p);
}
__device__ __forceinline__ unsigned long long dup2(float x) {
    unsigned long long r; asm("mov.b64 %0, {%1, %1};" : "=l"(r) : "f"(x)); return r;
}
#define CPASYNC(dst, src) asm volatile("cp.async.cg.shared.global [%0], [%1], 16;" :: "r"(dst), "l"(src))
#define CPCOMMIT()        asm volatile("cp.async.commit_group;")
#define CPWAIT(n)         asm volatile("cp.async.wait_group %0;" :: "n"(n) : "memory")

__device__ __forceinline__ void split2(float v, __nv_bfloat16& c0, __nv_bfloat16& c1) {
    c0 = __float2bfloat16_rn(v);
    c1 = __float2bfloat16_rn(v - __bfloat162float(c0));
}

// ======================= prep: split static into 2 bf16 components =======================
__global__ void prep_a2(const float4* __restrict__ src)
{
    size_t i = (size_t)blockIdx.x * blockDim.x + threadIdx.x;
    float4 v = src[i];
    __nv_bfloat16 a0[4], a1[4];
    split2(v.x, a0[0], a1[0]);
    split2(v.y, a0[1], a1[1]);
    split2(v.z, a0[2], a1[2]);
    split2(v.w, a0[3], a1[3]);
    ((__nv_bfloat162*)g_A0)[i*2]   = __halves2bfloat162(a0[0], a0[1]);
    ((__nv_bfloat162*)g_A0)[i*2+1] = __halves2bfloat162(a0[2], a0[3]);
    ((__nv_bfloat162*)g_A1)[i*2]   = __halves2bfloat162(a1[0], a1[1]);
    ((__nv_bfloat162*)g_A1)[i*2+1] = __halves2bfloat162(a1[2], a1[3]);
}

// ======================= prep: transpose + 2-split bottom half of w1 =======================
__global__ void prep_w2(const float* __restrict__ w1)
{
    __shared__ float tile[32][33];
    const int kb = blockIdx.x * 32, nb = blockIdx.y * 32;
    const int tx = threadIdx.x & 31, ty = threadIdx.x >> 5;
    #pragma unroll
    for (int r = 0; r < 32; r += 8)
        tile[ty + r][tx] = w1[(size_t)(DR2 + kb + ty + r) * DR2 + nb + tx];
    __syncthreads();
    #pragma unroll
    for (int r = 0; r < 32; r += 8) {
        int n = nb + ty + r, k = kb + tx;
        __nv_bfloat16 c0, c1;
        split2(tile[tx][ty + r], c0, c1);
        g_W0[(size_t)n * DR2 + k] = c0;
        g_W1[(size_t)n * DR2 + k] = c1;
    }
}

// ======================= pass 1: G = static @ W_bot (wmma bf16, 4 products) =======================
#define KP      40
#define ACOMP1  (128 * KP * 2)      // 10240 B per component
#define STG1    (4 * ACOMP1)        // A0|A1|B0|B1 = 40960 B
#define P1_SMEM (2 * STG1)          // 81920

__global__ void __launch_bounds__(256, 2)
pass1_kernel(float* __restrict__ C)
{
    extern __shared__ char sm[];
    const int tid = threadIdx.x;
    const int wid = tid >> 5;
    const size_t m0 = (size_t)blockIdx.y * 128;
    const size_t n0 = (size_t)blockIdx.x * 128;

    auto loadAB = [&](int c, int s) {
        char* S = sm + s * STG1;
        #pragma unroll
        for (int r = 0; r < 4; ++r) {
            int id = tid + r * 256;
            int comp = id >> 9, rem = id & 511;
            int row = rem >> 2, kq = rem & 3;
            const __nv_bfloat16* base = comp ? g_A1 : g_A0;
            const __nv_bfloat16* src = base + (m0 + row) * DR2 + c * 32 + kq * 8;
            CPASYNC(smem_u32(S + comp * ACOMP1 + row * (KP*2) + kq * 16), src);
        }
        #pragma unroll
        for (int r = 0; r < 4; ++r) {
            int id = tid + r * 256;
            int comp = id >> 9, rem = id & 511;
            int row = rem >> 2, kq = rem & 3;
            const __nv_bfloat16* base = comp ? g_W1 : g_W0;
            const __nv_bfloat16* src = base + (n0 + row) * DR2 + c * 32 + kq * 8;
            CPASYNC(smem_u32(S + 2 * ACOMP1 + comp * ACOMP1 + row * (KP*2) + kq * 16), src);
        }
        CPCOMMIT();
    };

    FragC acc[2][4];
    #pragma unroll
    for (int i = 0; i < 2; ++i)
        #pragma unroll
        for (int j = 0; j < 4; ++j) wmma::fill_fragment(acc[i][j], 0.0f);

    const int mw = (wid >> 1) * 32;
    const int nw = (wid & 1) * 64;

    loadAB(0, 0);
    for (int c = 0; c < 16; ++c) {
        if (c < 15) { loadAB(c + 1, (c + 1) & 1); CPWAIT(1); } else CPWAIT(0);
        __syncthreads();
        char* S = sm + (c & 1) * STG1;
        const __nv_bfloat16* A0 = (const __nv_bfloat16*)(S);
        const __nv_bfloat16* A1 = (const __nv_bfloat16*)(S + ACOMP1);
        const __nv_bfloat16* B0 = (const __nv_bfloat16*)(S + 2 * ACOMP1);
        const __nv_bfloat16* B1 = (const __nv_bfloat16*)(S + 3 * ACOMP1);
        #pragma unroll
        for (int ks = 0; ks < 2; ++ks) {
            FragA a0[2], a1[2];
            #pragma unroll
            for (int i = 0; i < 2; ++i) {
                int ro = (mw + i * 16) * KP + ks * 16;
                wmma::load_matrix_sync(a0[i], A0 + ro, KP);
                wmma::load_matrix_sync(a1[i], A1 + ro, KP);
            }
            #pragma unroll
            for (int j = 0; j < 4; ++j) {
                int ro = (nw + j * 16) * KP + ks * 16;
                FragB b0, b1;
                wmma::load_matrix_sync(b0, B0 + ro, KP);
                wmma::load_matrix_sync(b1, B1 + ro, KP);
                #pragma unroll
                for (int i = 0; i < 2; ++i) {
                    wmma::mma_sync(acc[i][j], a0[i], b0, acc[i][j]);
                    wmma::mma_sync(acc[i][j], a0[i], b1, acc[i][j]);
                    wmma::mma_sync(acc[i][j], a1[i], b0, acc[i][j]);
                    wmma::mma_sync(acc[i][j], a1[i], b1, acc[i][j]);
                }
            }
        }
        __syncthreads();
    }
    #pragma unroll
    for (int i = 0; i < 2; ++i)
        #pragma unroll
        for (int j = 0; j < 4; ++j)
            wmma::store_matrix_sync(C + (m0 + mw + i * 16) * DR2 + n0 + nw + j * 16,
                                    acc[i][j], DR2, wmma::mem_row_major);
}

// ======================= pass 2: fp32 recurrence, M_TILE=8, 2 CTAs/SM =======================
#define NTH2    256
#define MT2     8
#define XPITCH  516
#define KCQ     4               // k-rows per quarter per chunk
#define NCHK    32              // chunks per step
// smem float offsets
#define W_OFF   0               // 2 stages x 8192 floats (64KB); P aliases (4q x 8r x 512)
#define H_OFF   16384           // 8 x 516
#define G_OFF   (H_OFF + MT2 * XPITCH)
#define THR_OFF (G_OFF + MT2 * XPITCH)
#define SM2_BYTES ((THR_OFF + 8) * 4)   // ~98.6 KB -> 2 CTAs/SM

__global__ void __launch_bounds__(NTH2, 2)
evo_kernel(const float* __restrict__ g_thr,
           const float* __restrict__ g_h0,
           const float* __restrict__ g_w1,
           float* __restrict__ g_out)
{
    extern __shared__ char sm[];
    float* smf   = (float*)sm;
    float* w_sh  = smf + W_OFF;
    float* h_sh  = smf + H_OFF;
    float* g_sh  = smf + G_OFF;
    float* thr_s = smf + THR_OFF;

    float* out_dyn  = g_out;
    float* out_fin  = g_out + (size_t)T_STEPS * N_ROWS * DR2;
    float* out_diff = out_fin + (size_t)N_ROWS * DR2;

    const int tid = threadIdx.x;
    const int r0  = blockIdx.x * MT2;
    const int kq  = tid >> 6;          // k-quarter 0..3 (64 threads each; warps uniform)
    const int jt  = tid & 63;          // 8 cols (4 float2)

    auto loadW = [&](int c, int s) {   // one chunk: 4q x 4r x 512 = 8192 floats (32KB)
        unsigned dstb = smem_u32(w_sh + s * 8192);
        #pragma unroll
        for (int i = 0; i < 8; ++i) {
            int idx = tid + i * NTH2;
            int q = idx >> 9, rem = idx & 511;
            int r = rem >> 7, f4 = rem & 127;
            const char* src = (const char*)(g_w1 + ((size_t)(q * 128 + c * KCQ + r)) * DR2 + f4 * 4);
            CPASYNC(dstb + (unsigned)((q * 4 + r) * 512 + f4 * 4) * 4u, src);
        }
    };
    auto loadG = [&](int t) {          // G[t] tile -> g_sh
        #pragma unroll
        for (int i = 0; i < 4; ++i) {
            int idx = tid + i * NTH2;
            int row = idx >> 7, f4 = idx & 127;
            const char* src = (const char*)(out_dyn + ((size_t)t * N_ROWS + r0 + row) * DR2 + f4 * 4);
            CPASYNC(smem_u32(g_sh + row * XPITCH + f4 * 4), src);
        }
    };

    // ---- init: h0 -> h_sh ----
    {
        const float4* src = (const float4*)(g_h0 + (size_t)r0 * DR2);
        #pragma unroll
        for (int i = 0; i < 4; ++i) {
            int idx = tid + i * NTH2;
            int row = idx >> 7, f4 = idx & 127;
            *(float4*)(h_sh + row * XPITCH + f4 * 4) = src[idx];
        }
    }
    loadW(0, 0);
    loadG(0);
    CPCOMMIT();
    __syncthreads();

    unsigned long long acc[8][4];

    for (int t = 0; t < T_STEPS; ++t) {
        if (tid < MT2) thr_s[tid] = g_thr[(size_t)t * N_ROWS + r0 + tid];

        #pragma unroll
        for (int a = 0; a < 8; ++a)
            #pragma unroll
            for (int b = 0; b < 4; ++b) acc[a][b] = 0ull;

        for (int c = 0; c < NCHK; ++c) {
            if (c < NCHK - 1) { loadW(c + 1, (c + 1) & 1); CPCOMMIT(); CPWAIT(1); }
            else CPWAIT(0);
            __syncthreads();

            const float* wb = w_sh + (c & 1) * 8192 + kq * 2048;

            // x for this chunk: 8 rows x 4 kk (one broadcast LDS.128 per row)
            float4 xr[8];
            #pragma unroll
            for (int mi = 0; mi < 8; ++mi)
                xr[mi] = *(const float4*)(h_sh + mi * XPITCH + kq * 128 + c * KCQ);

            #pragma unroll
            for (int kk = 0; kk < KCQ; ++kk) {
                const unsigned long long* wrow = (const unsigned long long*)(wb + kk * 512);
                unsigned long long wv[4];
                #pragma unroll
                for (int jj = 0; jj < 4; ++jj) wv[jj] = wrow[jt + 64 * jj];
                #pragma unroll
                for (int mi = 0; mi < 8; ++mi) {
                    float xs = (kk == 0) ? xr[mi].x : (kk == 1) ? xr[mi].y
                             : (kk == 2) ? xr[mi].z : xr[mi].w;
                    unsigned long long xv = dup2(xs);
                    #pragma unroll
                    for (int jj = 0; jj < 4; ++jj)
                        asm("fma.rn.f32x2 %0, %1, %2, %0;"
                            : "+l"(acc[mi][jj]) : "l"(xv), "l"(wv[jj]));
                }
            }
            __syncthreads();
        }

        // ---- write partials to P (aliases both W stages: P[q] = w_sh + q*4096) ----
        {
            unsigned long long* P = (unsigned long long*)(w_sh + kq * 4096);
            #pragma unroll
            for (int mi = 0; mi < 8; ++mi)
                #pragma unroll
                for (int jj = 0; jj < 4; ++jj)
                    P[(mi * 512 + jt * 2 + 128 * jj) >> 1] = acc[mi][jj];
        }
        __syncthreads();

        // ---- gate: reduce 4 partials + G, sigmoid, update h, write outputs ----
        {
            int r = tid >> 5, cs = tid & 31;            // 32 threads per row
            float th = thr_s[r], om = 1.0f - th;
            size_t rowoff = (size_t)(r0 + r) * DR2;
            float* dynp  = out_dyn  + (size_t)t * N_ROWS * DR2 + rowoff;
            float* finp  = out_fin  + rowoff;
            float* diffp = out_diff + (size_t)(t - 1) * N_ROWS * DR2 + rowoff;
            #pragma unroll
            for (int w = 0; w < 4; ++w) {
                int col = cs * 4 + w * 128;             // consecutive float4 per lane
                float4 p0 = *(float4*)(w_sh + 0 * 4096 + r * 512 + col);
                float4 p1 = *(float4*)(w_sh + 1 * 4096 + r * 512 + col);
                float4 p2 = *(float4*)(w_sh + 2 * 4096 + r * 512 + col);
                float4 p3 = *(float4*)(w_sh + 3 * 4096 + r * 512 + col);
                float4 gg = *(float4*)(g_sh + r * XPITCH + col);
                float4 ho = *(float4*)(h_sh + r * XPITCH + col);
                float mm[4] = { p0.x + p1.x + p2.x + p3.x + gg.x,
                                p0.y + p1.y + p2.y + p3.y + gg.y,
                                p0.z + p1.z + p2.z + p3.z + gg.z,
                                p0.w + p1.w + p2.w + p3.w + gg.w };
                float hv[4] = { ho.x, ho.y, ho.z, ho.w };
                float nv[4];
                #pragma unroll
                for (int e = 0; e < 4; ++e)
                    nv[e] = DECAY_F / (1.0f + __expf(-(mm[e] * th + hv[e] * om)));
                *(float4*)(h_sh + r * XPITCH + col) = make_float4(nv[0], nv[1], nv[2], nv[3]);
                if (t > 0) {
                    *(float4*)(dynp + col)  = make_float4(nv[0], nv[1], nv[2], nv[3]);
                    *(float4*)(diffp + col) = make_float4(nv[0] - hv[0], nv[1] - hv[1],
                                                          nv[2] - hv[2], nv[3] - hv[3]);
                } else {
                    *(float4*)(dynp + col) = make_float4(hv[0], hv[1], hv[2], hv[3]);  // dyn[0]=h0
                }
                if (t == T_STEPS - 1)
                    *(float4*)(finp + col) = make_float4(nv[0], nv[1], nv[2], nv[3]);
            }
        }
        __syncthreads();

        // ---- tail prefetch: next step's W chunk 0 + G[t+1] ----
        if (t + 1 < T_STEPS) {
            loadW(0, 0);
            loadG(t + 1);
            CPCOMMIT();
        }
    }
}

extern "C" void kernel_launch(void* const* d_in, const int* in_sizes, int n_in,
                              void* d_out, int out_size)
{
    (void)in_sizes; (void)n_in; (void)out_size;
    const float* g_static = (const float*)d_in[0];
    const float* g_thr    = (const float*)d_in[1];
    const float* g_h0     = (const float*)d_in[2];
    const float* g_w1     = (const float*)d_in[3];
    float* out = (float*)d_out;

    // prep: 2-component bf16 splits
    prep_w2<<<dim3(DR2 / 32, DR2 / 32), 256>>>(g_w1);
    prep_a2<<<(T_STEPS * N_ROWS * DR2 / 4) / 256, 256>>>((const float4*)g_static);

    // pass 1: G = static @ W_bot (4 products) -> staged into dyn region
    cudaFuncSetAttribute(pass1_kernel, cudaFuncAttributeMaxDynamicSharedMemorySize, P1_SMEM);
    dim3 grid1(DR2 / 128, T_STEPS * N_ROWS / 128);
    pass1_kernel<<<grid1, 256, P1_SMEM>>>(out);

    // pass 2: fp32 recurrence, 2 CTAs/SM
    cudaFuncSetAttribute(evo_kernel, cudaFuncAttributeMaxDynamicSharedMemorySize, SM2_BYTES);
    evo_kernel<<<N_ROWS / MT2, NTH2, SM2_BYTES>>>(g_thr, g_h0, g_w1, out);
}